// round 10
// baseline (speedup 1.0000x reference)
#include <cuda_runtime.h>
#include <math.h>

#define NSC   48
#define RMAX  11
#define NCTA  (3*NSC)
#define T     384

#define GW0_F4 4864        // 38 pairs * 64 m * 2 f4
#define GW0_A  2560        // pairs 0..19
#define GW0_B  2304        // pairs 20..37
#define GW1_F4 8192        // 64 pairs * 64 m * 2 f4
#define PAN_F4 2560        // 40KB panel
#define DYN_SMEM ((GW1_F4 + PAN_F4) * 16)   // 172,032 bytes

typedef unsigned long long u64t;

__device__ float4 g_gw0p2[3*GW0_F4];
__device__ float4 g_gw1p2[3*GW1_F4];
__device__ __align__(16) float g_Wa_t[6*4096];
__device__ __align__(16) float g_w1_t[6*8192];
__device__ __align__(16) float g_w2_t[6*8192];
__device__ __align__(16) float g_rw1_t[3*4096];
__device__ float g_ba[6*64];
__device__ float g_outs[3ull*512*512*64];

__device__ __forceinline__ float sigmf(float v){
    return __fdividef(1.0f, 1.0f + __expf(-v));
}
__device__ __forceinline__ float tanhfast(float v){
    return 1.0f - __fdividef(2.0f, __expf(2.0f*v) + 1.0f);
}
__device__ __forceinline__ u64t fma2(u64t a, u64t b, u64t c){
    u64t d;
    asm("fma.rn.f32x2 %0, %1, %2, %3;" : "=l"(d) : "l"(a), "l"(b), "l"(c));
    return d;
}
__device__ __forceinline__ u64t pk2(float lo, float hi){
    u64t r; asm("mov.b64 %0, {%1, %2};" : "=l"(r) : "f"(lo), "f"(hi)); return r;
}
__device__ __forceinline__ float red2(u64t v){
    float lo, hi; asm("mov.b64 {%0, %1}, %2;" : "=f"(lo), "=f"(hi) : "l"(v)); return lo + hi;
}

template<int N>
__device__ __forceinline__ void cpyp(float4* d, const float4* __restrict__ s, int tid){
    #pragma unroll
    for (int i = 0; i < (N + T - 1)/T; i++){
        int j = tid + i*T;
        if (j < N) d[j] = s[j];
    }
}

// ---- pack gates into k-pair layout: [s][p][m][f0,f1,i0,i1,g0,g1,o0,o1] ----
__global__ void pack_gw_kernel(const float* __restrict__ gw0, const float* __restrict__ gw1){
    int i = blockIdx.x*blockDim.x + threadIdx.x;
    float* p0 = (float*)g_gw0p2;
    float* p1 = (float*)g_gw1p2;
    if (i < 3*76*256){
        int s = i/(76*256), rem = i%(76*256), k = rem/256, j = rem%256;
        int g = j>>6, m = j&63, p = k>>1, h = k&1;
        p0[(((s*38 + p)*64 + m)<<3) + (g<<1) + h] = gw0[i];
    }
    if (i < 3*128*256){
        int s = i/(128*256), rem = i%(128*256), k = rem/256, j = rem%256;
        int g = j>>6, m = j&63, p = k>>1, h = k&1;
        p1[(((s*64 + p)*64 + m)<<3) + (g<<1) + h] = gw1[i];
    }
}

// ---- pack stage weights into [p][colpair][wk0c0,wk1c0,wk0c1,wk1c1] ----
__global__ void pack_t_kernel(const float* __restrict__ w1, const float* __restrict__ w2,
                              const float* __restrict__ rw1){
    int i = blockIdx.x*blockDim.x + threadIdx.x;
    if (i < 6*64*128){
        int sl = i/(64*128), k = (i/128)%64, n = i%128;
        g_w1_t[((sl*32 + (k>>1))*64 + (n>>1))*4 + ((n&1)<<1) + (k&1)] = w1[i];
    }
    if (i < 6*128*64){
        int sl = i/(128*64), k = (i/64)%128, n = i%64;
        g_w2_t[((sl*64 + (k>>1))*32 + (n>>1))*4 + ((n&1)<<1) + (k&1)] = w2[i];
    }
    if (i < 3*64*64){
        int s = i/(64*64), k = (i/64)%64, n = i%64;
        g_rw1_t[((s*32 + (k>>1))*32 + (n>>1))*4 + ((n&1)<<1) + (k&1)] = rw1[i];
    }
}

__global__ void compute_wa_kernel(const float* __restrict__ mi_w, const float* __restrict__ mi_b,
                                  const float* __restrict__ mo_w, const float* __restrict__ mo_b){
    int sl = blockIdx.x;
    const float* miw = mi_w + (size_t)sl*64*192;
    const float* mow = mo_w + (size_t)sl*64*64;
    for (int idx = threadIdx.x; idx < 64*64; idx += blockDim.x){
        int k = idx>>6, n = idx&63;
        float acc = 0.f;
        #pragma unroll 8
        for (int j=0;j<64;j++) acc += miw[k*192 + 128 + j] * mow[j*64 + n];
        g_Wa_t[((sl*32 + (k>>1))*32 + (n>>1))*4 + ((n&1)<<1) + (k&1)] = acc;
    }
    if (threadIdx.x < 64){
        int n = threadIdx.x;
        float acc = mo_b[sl*64 + n];
        #pragma unroll 8
        for (int j=0;j<64;j++) acc += mi_b[sl*192 + 128 + j] * mow[j*64 + n];
        g_ba[sl*64 + n] = acc;
    }
}

__global__ void __launch_bounds__(T, 1) xlstm_kernel(
    const float* __restrict__ x,
    const float* __restrict__ gb0, const float* __restrict__ gb1,
    const float* __restrict__ b1,  const float* __restrict__ b2,
    const float* __restrict__ lag, const float* __restrict__ lab,
    const float* __restrict__ logw,const float* __restrict__ lob,
    const float* __restrict__ rw0, const float* __restrict__ rb0,
    const float* __restrict__ rb1)
{
    const int cta = blockIdx.x;
    const int s   = cta / NSC;
    const int ci  = cta % NSC;
    const int base  = (ci < 32) ? ci*11 : 352 + (ci-32)*10;
    const int nrows = (ci < 32) ? 11 : 10;
    const int tid  = threadIdx.x;
    const int m    = tid & 63;
    const int rg   = tid >> 6;
    const int lane = tid & 31;
    const int wrp  = tid >> 5;
    const int cg   = tid & 31;
    const int m2   = cg*2;
    const int cgf  = tid & 63;
    const int n2b  = cgf*2;
    const int rgf  = tid >> 6;

    extern __shared__ float4 dynsm[];
    float4* s_gw1 = dynsm;               // resident 128KB (k-pair layout)
    float4* pan4  = dynsm + GW1_F4;      // 40KB panel
    const ulonglong2* gw1u = (const ulonglong2*)s_gw1;
    const ulonglong2* panu = (const ulonglong2*)pan4;

    __shared__ __align__(16) float sh_h0[RMAX][64], sh_h1[RMAX][64];
    __shared__ __align__(16) float sh_x[RMAX][12];
    __shared__ __align__(16) float sh_hy[RMAX][64];
    __shared__ __align__(16) float sh_a[RMAX][64];
    __shared__ __align__(16) float sh_t1[RMAX][128];
    __shared__ __align__(16) float sh_inp[RMAX][64];
    __shared__ float sh_stat[RMAX][2];
    __shared__ __align__(16) float sb_ba[2][64];
    __shared__ __align__(16) float sb_b1[2][128];
    __shared__ __align__(16) float sb_b2[2][64];
    __shared__ __align__(16) float sb_rb1[64];
    __shared__ __align__(16) float s_rw0[12*64];
    __shared__ __align__(16) float s_rw1[64*64];   // k-pair transposed layout

    {
        const float4* g1 = g_gw1p2 + (size_t)s*GW1_F4;
        for (int i=tid;i<GW1_F4;i+=T) s_gw1[i] = g1[i];
        const float* rw1s = g_rw1_t + (size_t)s*4096;
        for (int i=tid;i<4096;i+=T) s_rw1[i] = rw1s[i];
        const float* rw0s = rw0 + (size_t)s*768;
        for (int i=tid;i<768;i+=T) s_rw0[i] = rw0s[i];
        for (int i = tid; i < RMAX*64; i += T){ ((float*)sh_h0)[i] = 0.f; ((float*)sh_h1)[i] = 0.f; }
        if (tid < 128){
            sb_b1[0][tid] = b1[(s*2+0)*128 + tid];
            sb_b1[1][tid] = b1[(s*2+1)*128 + tid];
        }
        if (tid < 64){
            sb_ba[0][tid] = g_ba[(s*2+0)*64 + tid];
            sb_ba[1][tid] = g_ba[(s*2+1)*64 + tid];
            sb_b2[0][tid] = b2[(s*2+0)*64 + tid];
            sb_b2[1][tid] = b2[(s*2+1)*64 + tid];
            sb_rb1[tid]   = rb1[s*64 + tid];
        }
    }
    const float r_gb0f = gb0[s*256 + m],     r_gb0i = gb0[s*256 + 64 + m];
    const float r_gb0g = gb0[s*256 + 128+m], r_gb0o = gb0[s*256 + 192 + m];
    const float r_gb1f = gb1[s*256 + m],     r_gb1i = gb1[s*256 + 64 + m];
    const float r_gb1g = gb1[s*256 + 128+m], r_gb1o = gb1[s*256 + 192 + m];
    const float r_lag0 = lag[(s*2+0)*64+m],  r_lag1 = lag[(s*2+1)*64+m];
    const float r_lab0 = lab[(s*2+0)*64+m],  r_lab1 = lab[(s*2+1)*64+m];
    const float r_log0 = logw[(s*2+0)*64+m], r_log1 = logw[(s*2+1)*64+m];
    const float r_lob0 = lob[(s*2+0)*64+m],  r_lob1 = lob[(s*2+1)*64+m];
    const float r_rb0  = rb0[s*64+m];
    __syncthreads();

    int myr[2]; int nmy = 0;
    #pragma unroll
    for (int q=0;q<2;q++){ int r = rg + 6*q; myr[q] = (r < nrows) ? r : (nrows-1); if (r < nrows) nmy = q+1; }
    const int rA = rgf;
    const int rBr = rgf + 6;
    const bool hasB = (rBr < nrows);
    const int rB = hasB ? rBr : 0;

    float c0r[2] = {0.f,0.f}, c1r[2] = {0.f,0.f};

    const float4* gw0g  = g_gw0p2 + (size_t)s*GW0_F4;
    const float4* Wa0_4 = (const float4*)g_Wa_t + (size_t)(s*2+0)*1024;
    const float4* Wa1_4 = (const float4*)g_Wa_t + (size_t)(s*2+1)*1024;
    const float4* w10_4 = (const float4*)g_w1_t + (size_t)(s*2+0)*2048;
    const float4* w11_4 = (const float4*)g_w1_t + (size_t)(s*2+1)*2048;
    const float4* w20_4 = (const float4*)g_w2_t + (size_t)(s*2+0)*2048;
    const float4* w21_4 = (const float4*)g_w2_t + (size_t)(s*2+1)*2048;

    const int Li  = (s==0) ? 170 : (s==1 ? 512 : 256);
    const int st0 = (s==0) ? 342 : (s==1 ? 0   : 256);
    const float scf = (float)Li / 512.0f;

    float* outbase = g_outs + ((size_t)s*512 + base)*512*64;

    auto ln_pass = [&](){
        if (wrp < nrows){
            int r = wrp;
            float va = sh_hy[r][lane], vb = sh_hy[r][lane+32];
            float sm = va + vb, sq = va*va + vb*vb;
            #pragma unroll
            for (int o=16;o;o>>=1){
                sm += __shfl_xor_sync(0xffffffffu, sm, o);
                sq += __shfl_xor_sync(0xffffffffu, sq, o);
            }
            if (lane == 0){
                float mean = sm * 0.015625f;
                float var  = sq * 0.015625f - mean*mean;
                sh_stat[r][0] = mean;
                sh_stat[r][1] = rsqrtf(var + 1e-5f);
            }
        }
    };
    auto ln_chain = [&](float (*hstate)[64], float* hn_out,
                        float lag_r, float lab_r, float log_r, float lob_r){
        ln_pass();
        __syncthreads();
        #pragma unroll
        for (int q=0;q<2;q++){
            int r = myr[q];
            float v  = sh_hy[r][m];
            float ln = (v - sh_stat[r][0]) * sh_stat[r][1] * lag_r + lab_r;
            float yv = ln + hstate[r][m];
            if (q < nmy) sh_hy[r][m] = yv;
        }
        __syncthreads();
        ln_pass();
        __syncthreads();
        #pragma unroll
        for (int q=0;q<2;q++){
            int r = myr[q];
            float yv = sh_hy[r][m];
            float hn = (yv - sh_stat[r][0]) * sh_stat[r][1] * log_r + lob_r;
            hn_out[q] = hn;
            if (q < nmy) hstate[r][m] = hn;
        }
    };

    // attn: a[r][m2..m2+1] = ba + hy[r]@Wa  (32 k-pairs, f32x2)
    auto attn_stage = [&](int l){
        if (wrp < nrows){
            int r = wrp;
            u64t a0 = pk2(sb_ba[l][m2], 0.f), a1 = pk2(sb_ba[l][m2+1], 0.f);
            #pragma unroll 8
            for (int p=0;p<32;p++){
                ulonglong2 w = panu[p*32 + cg];
                u64t z = *(const u64t*)&sh_hy[r][2*p];
                a0 = fma2(z, w.x, a0);
                a1 = fma2(z, w.y, a1);
            }
            *(float2*)&sh_a[r][m2] = make_float2(red2(a0), red2(a1));
        }
    };
    auto ff1_stage = [&](int l){
        u64t t00 = pk2(sb_b1[l][n2b], 0.f), t01 = pk2(sb_b1[l][n2b+1], 0.f);
        u64t t10 = t00, t11 = t01;
        #pragma unroll 8
        for (int p=0;p<32;p++){
            ulonglong2 w = panu[p*64 + cgf];
            u64t zA = *(const u64t*)&sh_a[rA][2*p];
            u64t zB = *(const u64t*)&sh_a[rB][2*p];
            t00 = fma2(zA, w.x, t00); t01 = fma2(zA, w.y, t01);
            t10 = fma2(zB, w.x, t10); t11 = fma2(zB, w.y, t11);
        }
        const float c = 0.7071067811865475f;
        float v00 = red2(t00), v01 = red2(t01), v10 = red2(t10), v11 = red2(t11);
        float g00 = 0.5f*v00*(1.0f + erff(v00*c));
        float g01 = 0.5f*v01*(1.0f + erff(v01*c));
        *(float2*)&sh_t1[rA][n2b] = make_float2(g00, g01);
        if (hasB){
            float g10 = 0.5f*v10*(1.0f + erff(v10*c));
            float g11 = 0.5f*v11*(1.0f + erff(v11*c));
            *(float2*)&sh_t1[rB][n2b] = make_float2(g10, g11);
        }
    };
    auto ff2_stage = [&](int l){
        if (wrp < nrows){
            int r = wrp;
            u64t a0 = pk2(sb_b2[l][m2], 0.f), a1 = pk2(sb_b2[l][m2+1], 0.f);
            #pragma unroll 8
            for (int p=0;p<64;p++){
                ulonglong2 w = panu[p*32 + cg];
                u64t z = *(const u64t*)&sh_t1[r][2*p];
                a0 = fma2(z, w.x, a0);
                a1 = fma2(z, w.y, a1);
            }
            *(float2*)&sh_hy[r][m2] = make_float2(red2(a0), red2(a1));
        }
    };

    for (int t=0; t<512; t++){
        cpyp<GW0_A>(pan4, gw0g, tid);
        {
            float srcf = fmaxf((t + 0.5f) * scf - 0.5f, 0.0f);
            int i0 = (int)srcf;
            if (i0 > Li-1) i0 = Li-1;
            int i1 = min(i0+1, Li-1);
            float wu = srcf - (float)i0;
            if (tid < nrows*12){
                int r = tid/12, k = tid%12;
                const float* xb = x + ((size_t)(base+r)*512 + st0)*12;
                float va = xb[i0*12 + k], vb = xb[i1*12 + k];
                sh_x[r][k] = va*(1.0f - wu) + vb*wu;
            }
        }
        __syncthreads();                              // S1: gw0A(pairs0..19) + sh_x ready

        // ---- gates layer 0 (f32x2, even/odd split) ----
        u64t aF[2], aI[2], aG[2], aO[2];
        #pragma unroll
        for (int q=0;q<2;q++){
            aF[q] = pk2(r_gb0f, 0.f); aI[q] = pk2(r_gb0i, 0.f);
            aG[q] = pk2(r_gb0g, 0.f); aO[q] = pk2(r_gb0o, 0.f);
        }
        #pragma unroll
        for (int p=0;p<6;p++){                        // k 0..11 from sh_x
            ulonglong2 wfi = panu[(p*64+m)*2], wgo = panu[(p*64+m)*2+1];
            #pragma unroll
            for (int q=0;q<2;q++){
                u64t z = *(const u64t*)&sh_x[myr[q]][2*p];
                aF[q] = fma2(z, wfi.x, aF[q]); aI[q] = fma2(z, wfi.y, aI[q]);
                aG[q] = fma2(z, wgo.x, aG[q]); aO[q] = fma2(z, wgo.y, aO[q]);
            }
        }
        #pragma unroll 7
        for (int p=6;p<20;p++){                       // k 12..39 from sh_h0
            ulonglong2 wfi = panu[(p*64+m)*2], wgo = panu[(p*64+m)*2+1];
            #pragma unroll
            for (int q=0;q<2;q++){
                u64t z = *(const u64t*)&sh_h0[myr[q]][2*p-12];
                aF[q] = fma2(z, wfi.x, aF[q]); aI[q] = fma2(z, wfi.y, aI[q]);
                aG[q] = fma2(z, wgo.x, aG[q]); aO[q] = fma2(z, wgo.y, aO[q]);
            }
        }
        __syncthreads();                              // S2: panel free
        cpyp<GW0_B>(pan4, gw0g + GW0_A, tid);
        __syncthreads();                              // S3: gw0B(pairs20..37) ready
        #pragma unroll 6
        for (int p=20;p<38;p++){                      // k 40..75 from sh_h0
            ulonglong2 wfi = panu[((p-20)*64+m)*2], wgo = panu[((p-20)*64+m)*2+1];
            #pragma unroll
            for (int q=0;q<2;q++){
                u64t z = *(const u64t*)&sh_h0[myr[q]][2*p-12];
                aF[q] = fma2(z, wfi.x, aF[q]); aI[q] = fma2(z, wfi.y, aI[q]);
                aG[q] = fma2(z, wgo.x, aG[q]); aO[q] = fma2(z, wgo.y, aO[q]);
            }
        }
        #pragma unroll
        for (int q=0;q<2;q++){
            float cn = sigmf(red2(aF[q]))*c0r[q] + sigmf(red2(aI[q]))*tanhfast(red2(aG[q]));
            float ht = sigmf(red2(aO[q]))*tanhfast(cn);
            if (q < nmy){ c0r[q] = cn; sh_hy[myr[q]][m] = ht; }
        }
        __syncthreads();                              // S4
        cpyp<1024>(pan4, Wa0_4, tid);
        __syncthreads();                              // S5
        attn_stage(0);
        __syncthreads();                              // S6
        cpyp<2048>(pan4, w10_4, tid);
        __syncthreads();                              // S7
        ff1_stage(0);
        __syncthreads();                              // S8
        cpyp<2048>(pan4, w20_4, tid);
        __syncthreads();                              // S9
        ff2_stage(0);
        __syncthreads();                              // S10
        float h0n[2];
        ln_chain(sh_h0, h0n, r_lag0, r_lab0, r_log0, r_lob0);
        #pragma unroll
        for (int q=0;q<2;q++){
            int r = myr[q];
            float acc = h0n[q] + r_rb0;
            #pragma unroll
            for (int k=0;k<12;k++) acc += sh_x[r][k] * s_rw0[k*64 + m];
            if (q < nmy) sh_inp[r][m] = acc;
        }
        __syncthreads();                              // S14
        cpyp<1024>(pan4, Wa1_4, tid);

        // ---- gates layer 1 (resident, f32x2) ----
        #pragma unroll
        for (int q=0;q<2;q++){
            aF[q] = pk2(r_gb1f, 0.f); aI[q] = pk2(r_gb1i, 0.f);
            aG[q] = pk2(r_gb1g, 0.f); aO[q] = pk2(r_gb1o, 0.f);
        }
        #pragma unroll 8
        for (int p=0;p<32;p++){                       // k 0..63 from sh_inp
            ulonglong2 wfi = gw1u[(p*64+m)*2], wgo = gw1u[(p*64+m)*2+1];
            #pragma unroll
            for (int q=0;q<2;q++){
                u64t z = *(const u64t*)&sh_inp[myr[q]][2*p];
                aF[q] = fma2(z, wfi.x, aF[q]); aI[q] = fma2(z, wfi.y, aI[q]);
                aG[q] = fma2(z, wgo.x, aG[q]); aO[q] = fma2(z, wgo.y, aO[q]);
            }
        }
        #pragma unroll 8
        for (int p=32;p<64;p++){                      // k 64..127 from sh_h1
            ulonglong2 wfi = gw1u[(p*64+m)*2], wgo = gw1u[(p*64+m)*2+1];
            #pragma unroll
            for (int q=0;q<2;q++){
                u64t z = *(const u64t*)&sh_h1[myr[q]][2*p-64];
                aF[q] = fma2(z, wfi.x, aF[q]); aI[q] = fma2(z, wfi.y, aI[q]);
                aG[q] = fma2(z, wgo.x, aG[q]); aO[q] = fma2(z, wgo.y, aO[q]);
            }
        }
        #pragma unroll
        for (int q=0;q<2;q++){
            float cn = sigmf(red2(aF[q]))*c1r[q] + sigmf(red2(aI[q]))*tanhfast(red2(aG[q]));
            float ht = sigmf(red2(aO[q]))*tanhfast(cn);
            if (q < nmy){ c1r[q] = cn; sh_hy[myr[q]][m] = ht; }
        }
        __syncthreads();                              // S15: Wa1 + hy ready
        attn_stage(1);
        __syncthreads();                              // S16
        cpyp<2048>(pan4, w11_4, tid);
        __syncthreads();                              // S17
        ff1_stage(1);
        __syncthreads();                              // S18
        cpyp<2048>(pan4, w21_4, tid);
        __syncthreads();                              // S19
        ff2_stage(1);
        __syncthreads();                              // S20
        float h1n[2];
        ln_chain(sh_h1, h1n, r_lag1, r_lab1, r_log1, r_lob1);
        __syncthreads();                              // S24

        // ---- out = h1 + inp@rw1 + rb1 (f32x2, resident transposed rw1) ----
        if (wrp < nrows){
            int r = wrp;
            u64t a0 = pk2(sb_rb1[m2]   + sh_h1[r][m2],   0.f);
            u64t a1 = pk2(sb_rb1[m2+1] + sh_h1[r][m2+1], 0.f);
            const ulonglong2* rwu = (const ulonglong2*)s_rw1;
            #pragma unroll 8
            for (int p=0;p<32;p++){
                ulonglong2 w = rwu[p*32 + cg];
                u64t z = *(const u64t*)&sh_inp[r][2*p];
                a0 = fma2(z, w.x, a0);
                a1 = fma2(z, w.y, a1);
            }
            ((float2*)(outbase + ((size_t)r*512 + t)*64))[cg] = make_float2(red2(a0), red2(a1));
        }
        __syncthreads();                              // S25
    }
}

__global__ void merge_kernel(const float* __restrict__ attn_w, float* __restrict__ out){
    int warp = (blockIdx.x*blockDim.x + threadIdx.x) >> 5;
    int lane = threadIdx.x & 31;
    if (warp >= 512*512) return;
    const size_t SS = 512ull*512*64;
    const float* p = g_outs + (size_t)warp*64;
    float aw0 = attn_w[lane], aw1 = attn_w[lane+32];
    float v0[3], v1[3], sc[3];
    #pragma unroll
    for (int si=0; si<3; si++){
        v0[si] = p[si*SS + lane];
        v1[si] = p[si*SS + lane + 32];
        float d = v0[si]*aw0 + v1[si]*aw1;
        #pragma unroll
        for (int o=16;o;o>>=1) d += __shfl_xor_sync(0xffffffffu, d, o);
        sc[si] = d;
    }
    float mx = fmaxf(sc[0], fmaxf(sc[1], sc[2]));
    float e0 = __expf(sc[0]-mx), e1 = __expf(sc[1]-mx), e2 = __expf(sc[2]-mx);
    float inv = __fdividef(1.0f, e0+e1+e2);
    float wt0 = e0*inv, wt1 = e1*inv, wt2 = e2*inv;
    out[(size_t)warp*64 + lane]      = v0[0]*wt0 + v0[1]*wt1 + v0[2]*wt2;
    out[(size_t)warp*64 + lane + 32] = v1[0]*wt0 + v1[1]*wt1 + v1[2]*wt2;
}

extern "C" void kernel_launch(void* const* d_in, const int* in_sizes, int n_in,
                              void* d_out, int out_size){
    const float* x     = (const float*)d_in[0];
    const float* gw0   = (const float*)d_in[1];
    const float* gb0   = (const float*)d_in[2];
    const float* gw1   = (const float*)d_in[3];
    const float* gb1   = (const float*)d_in[4];
    const float* mi_w  = (const float*)d_in[5];
    const float* mi_b  = (const float*)d_in[6];
    const float* mo_w  = (const float*)d_in[7];
    const float* mo_b  = (const float*)d_in[8];
    const float* w1    = (const float*)d_in[9];
    const float* b1    = (const float*)d_in[10];
    const float* w2    = (const float*)d_in[11];
    const float* b2    = (const float*)d_in[12];
    const float* lag   = (const float*)d_in[13];
    const float* lab   = (const float*)d_in[14];
    const float* logw  = (const float*)d_in[15];
    const float* lob   = (const float*)d_in[16];
    const float* rw0   = (const float*)d_in[17];
    const float* rb0   = (const float*)d_in[18];
    const float* rw1   = (const float*)d_in[19];
    const float* rb1   = (const float*)d_in[20];
    const float* attnw = (const float*)d_in[21];
    float* out = (float*)d_out;

    static int smem_set = 0;
    if (!smem_set){
        cudaFuncSetAttribute(xlstm_kernel, cudaFuncAttributeMaxDynamicSharedMemorySize, DYN_SMEM);
        smem_set = 1;
    }

    pack_gw_kernel<<<(3*128*256 + 255)/256, 256>>>(gw0, gw1);
    pack_t_kernel<<<(6*64*128 + 255)/256, 256>>>(w1, w2, rw1);
    compute_wa_kernel<<<6, 256>>>(mi_w, mi_b, mo_w, mo_b);
    xlstm_kernel<<<NCTA, T, DYN_SMEM>>>(x, gb0, gb1, b1, b2,
                                        lag, lab, logw, lob, rw0, rb0, rb1);
    merge_kernel<<<(512*512*32 + 255)/256, 256>>>(attnw, out);
}

// round 11
// speedup vs baseline: 1.2149x; 1.2149x over previous
#include <cuda_runtime.h>
#include <math.h>

#define NSC   48
#define RMAX  11
#define NCTA  (3*NSC)
#define T     384

#define GW0_F4 4864        // 38 pairs * 512B = 77,824B = 4864 f4
#define GW0_A  2560        // pairs 0..19  (20*512B = 40KB)
#define GW0_B  2304        // pairs 20..37 (18*512B = 36KB)
#define GW1_F4 8192        // 64 pairs * 512B = 128KB
#define PAN_F4 2560        // 40KB panel
#define DYN_SMEM ((GW1_F4 + PAN_F4) * 16)   // 172,032 bytes

typedef unsigned long long u64t;

__device__ float4 g_gw0p2[3*GW0_F4];
__device__ float4 g_gw1p2[3*GW1_F4];
__device__ __align__(16) float g_Wa_t[6*4096];
__device__ __align__(16) float g_w1_t[6*8192];
__device__ __align__(16) float g_w2_t[6*8192];
__device__ __align__(16) float g_rw1_t[3*4096];
__device__ float g_ba[6*64];
__device__ float g_outs[3ull*512*512*64];

__device__ __forceinline__ float sigmf(float v){
    return __fdividef(1.0f, 1.0f + __expf(-v));
}
__device__ __forceinline__ float tanhfast(float v){
    return 1.0f - __fdividef(2.0f, __expf(2.0f*v) + 1.0f);
}
__device__ __forceinline__ u64t fma2(u64t a, u64t b, u64t c){
    u64t d;
    asm("fma.rn.f32x2 %0, %1, %2, %3;" : "=l"(d) : "l"(a), "l"(b), "l"(c));
    return d;
}
__device__ __forceinline__ u64t pk2(float lo, float hi){
    u64t r; asm("mov.b64 %0, {%1, %2};" : "=l"(r) : "f"(lo), "f"(hi)); return r;
}
__device__ __forceinline__ float red2(u64t v){
    float lo, hi; asm("mov.b64 {%0, %1}, %2;" : "=f"(lo), "=f"(hi) : "l"(v)); return lo + hi;
}

template<int N>
__device__ __forceinline__ void cpyp(float4* d, const float4* __restrict__ s, int tid){
    #pragma unroll
    for (int i = 0; i < (N + T - 1)/T; i++){
        int j = tid + i*T;
        if (j < N) d[j] = s[j];
    }
}

// ---- pack gates: per k-pair block of 512B: FI plane [64 x {f_e,f_o,i_e,i_o}]
//      then GO plane [64 x {g_e,g_o,o_e,o_o}]  -> lane loads contiguous 16B ----
__global__ void pack_gw_kernel(const float* __restrict__ gw0, const float* __restrict__ gw1){
    int i = blockIdx.x*blockDim.x + threadIdx.x;
    float* p0 = (float*)g_gw0p2;
    float* p1 = (float*)g_gw1p2;
    if (i < 3*76*256){
        int s = i/(76*256), rem = i%(76*256), k = rem/256, j = rem%256;
        int g = j>>6, m = j&63, p = k>>1, h = k&1;
        int plane = g>>1;
        p0[(s*38 + p)*512 + plane*256 + m*4 + ((g&1)<<1) + h] = gw0[i];
    }
    if (i < 3*128*256){
        int s = i/(128*256), rem = i%(128*256), k = rem/256, j = rem%256;
        int g = j>>6, m = j&63, p = k>>1, h = k&1;
        int plane = g>>1;
        p1[(s*64 + p)*512 + plane*256 + m*4 + ((g&1)<<1) + h] = gw1[i];
    }
}

// ---- pack stage weights into [p][colpair][wk0c0,wk1c0,wk0c1,wk1c1] ----
__global__ void pack_t_kernel(const float* __restrict__ w1, const float* __restrict__ w2,
                              const float* __restrict__ rw1){
    int i = blockIdx.x*blockDim.x + threadIdx.x;
    if (i < 6*64*128){
        int sl = i/(64*128), k = (i/128)%64, n = i%128;
        g_w1_t[((sl*32 + (k>>1))*64 + (n>>1))*4 + ((n&1)<<1) + (k&1)] = w1[i];
    }
    if (i < 6*128*64){
        int sl = i/(128*64), k = (i/64)%128, n = i%64;
        g_w2_t[((sl*64 + (k>>1))*32 + (n>>1))*4 + ((n&1)<<1) + (k&1)] = w2[i];
    }
    if (i < 3*64*64){
        int s = i/(64*64), k = (i/64)%64, n = i%64;
        g_rw1_t[((s*32 + (k>>1))*32 + (n>>1))*4 + ((n&1)<<1) + (k&1)] = rw1[i];
    }
}

__global__ void compute_wa_kernel(const float* __restrict__ mi_w, const float* __restrict__ mi_b,
                                  const float* __restrict__ mo_w, const float* __restrict__ mo_b){
    int sl = blockIdx.x;
    const float* miw = mi_w + (size_t)sl*64*192;
    const float* mow = mo_w + (size_t)sl*64*64;
    for (int idx = threadIdx.x; idx < 64*64; idx += blockDim.x){
        int k = idx>>6, n = idx&63;
        float acc = 0.f;
        #pragma unroll 8
        for (int j=0;j<64;j++) acc += miw[k*192 + 128 + j] * mow[j*64 + n];
        g_Wa_t[((sl*32 + (k>>1))*32 + (n>>1))*4 + ((n&1)<<1) + (k&1)] = acc;
    }
    if (threadIdx.x < 64){
        int n = threadIdx.x;
        float acc = mo_b[sl*64 + n];
        #pragma unroll 8
        for (int j=0;j<64;j++) acc += mi_b[sl*192 + 128 + j] * mow[j*64 + n];
        g_ba[sl*64 + n] = acc;
    }
}

__global__ void __launch_bounds__(T, 1) xlstm_kernel(
    const float* __restrict__ x,
    const float* __restrict__ gb0, const float* __restrict__ gb1,
    const float* __restrict__ b1,  const float* __restrict__ b2,
    const float* __restrict__ lag, const float* __restrict__ lab,
    const float* __restrict__ logw,const float* __restrict__ lob,
    const float* __restrict__ rw0, const float* __restrict__ rb0,
    const float* __restrict__ rb1)
{
    const int cta = blockIdx.x;
    const int s   = cta / NSC;
    const int ci  = cta % NSC;
    const int base  = (ci < 32) ? ci*11 : 352 + (ci-32)*10;
    const int nrows = (ci < 32) ? 11 : 10;
    const int tid  = threadIdx.x;
    const int m    = tid & 63;
    const int rg   = tid >> 6;
    const int lane = tid & 31;
    const int wrp  = tid >> 5;
    const int cg   = tid & 31;
    const int m2   = cg*2;
    const int cgf  = tid & 63;
    const int n2b  = cgf*2;
    const int rgf  = tid >> 6;

    extern __shared__ float4 dynsm[];
    float4* s_gw1 = dynsm;               // resident 128KB (plane-split pairs)
    float4* pan4  = dynsm + GW1_F4;      // 40KB panel
    const ulonglong2* gw1u = (const ulonglong2*)s_gw1;
    const ulonglong2* panu = (const ulonglong2*)pan4;

    __shared__ __align__(16) float sh_h0[RMAX][64], sh_h1[RMAX][64];
    __shared__ __align__(16) float sh_x[RMAX][12];
    __shared__ __align__(16) float sh_hy[RMAX][64];
    __shared__ __align__(16) float sh_a[RMAX][64];
    __shared__ __align__(16) float sh_t1[RMAX][128];
    __shared__ __align__(16) float sh_inp[RMAX][64];
    __shared__ float sh_stat[RMAX][2];
    __shared__ __align__(16) float sb_ba[2][64];
    __shared__ __align__(16) float sb_b1[2][128];
    __shared__ __align__(16) float sb_b2[2][64];
    __shared__ __align__(16) float sb_rb1[64];
    __shared__ __align__(16) float s_rw0[12*64];
    __shared__ __align__(16) float s_rw1[64*64];   // k-pair transposed layout

    {
        const float4* g1 = g_gw1p2 + (size_t)s*GW1_F4;
        for (int i=tid;i<GW1_F4;i+=T) s_gw1[i] = g1[i];
        const float* rw1s = g_rw1_t + (size_t)s*4096;
        for (int i=tid;i<4096;i+=T) s_rw1[i] = rw1s[i];
        const float* rw0s = rw0 + (size_t)s*768;
        for (int i=tid;i<768;i+=T) s_rw0[i] = rw0s[i];
        for (int i = tid; i < RMAX*64; i += T){ ((float*)sh_h0)[i] = 0.f; ((float*)sh_h1)[i] = 0.f; }
        if (tid < 128){
            sb_b1[0][tid] = b1[(s*2+0)*128 + tid];
            sb_b1[1][tid] = b1[(s*2+1)*128 + tid];
        }
        if (tid < 64){
            sb_ba[0][tid] = g_ba[(s*2+0)*64 + tid];
            sb_ba[1][tid] = g_ba[(s*2+1)*64 + tid];
            sb_b2[0][tid] = b2[(s*2+0)*64 + tid];
            sb_b2[1][tid] = b2[(s*2+1)*64 + tid];
            sb_rb1[tid]   = rb1[s*64 + tid];
        }
    }
    const float r_gb0f = gb0[s*256 + m],     r_gb0i = gb0[s*256 + 64 + m];
    const float r_gb0g = gb0[s*256 + 128+m], r_gb0o = gb0[s*256 + 192 + m];
    const float r_gb1f = gb1[s*256 + m],     r_gb1i = gb1[s*256 + 64 + m];
    const float r_gb1g = gb1[s*256 + 128+m], r_gb1o = gb1[s*256 + 192 + m];
    const float r_lag0 = lag[(s*2+0)*64+m],  r_lag1 = lag[(s*2+1)*64+m];
    const float r_lab0 = lab[(s*2+0)*64+m],  r_lab1 = lab[(s*2+1)*64+m];
    const float r_log0 = logw[(s*2+0)*64+m], r_log1 = logw[(s*2+1)*64+m];
    const float r_lob0 = lob[(s*2+0)*64+m],  r_lob1 = lob[(s*2+1)*64+m];
    const float r_rb0  = rb0[s*64+m];
    __syncthreads();

    int myr[2]; int nmy = 0;
    #pragma unroll
    for (int q=0;q<2;q++){ int r = rg + 6*q; myr[q] = (r < nrows) ? r : (nrows-1); if (r < nrows) nmy = q+1; }
    const int rA = rgf;
    const int rBr = rgf + 6;
    const bool hasB = (rBr < nrows);
    const int rB = hasB ? rBr : 0;

    float c0r[2] = {0.f,0.f}, c1r[2] = {0.f,0.f};

    const float4* gw0g  = g_gw0p2 + (size_t)s*GW0_F4;
    const float4* Wa0_4 = (const float4*)g_Wa_t + (size_t)(s*2+0)*1024;
    const float4* Wa1_4 = (const float4*)g_Wa_t + (size_t)(s*2+1)*1024;
    const float4* w10_4 = (const float4*)g_w1_t + (size_t)(s*2+0)*2048;
    const float4* w11_4 = (const float4*)g_w1_t + (size_t)(s*2+1)*2048;
    const float4* w20_4 = (const float4*)g_w2_t + (size_t)(s*2+0)*2048;
    const float4* w21_4 = (const float4*)g_w2_t + (size_t)(s*2+1)*2048;

    const int Li  = (s==0) ? 170 : (s==1 ? 512 : 256);
    const int st0 = (s==0) ? 342 : (s==1 ? 0   : 256);
    const float scf = (float)Li / 512.0f;

    float* outbase = g_outs + ((size_t)s*512 + base)*512*64;

    auto ln_pass = [&](){
        if (wrp < nrows){
            int r = wrp;
            float va = sh_hy[r][lane], vb = sh_hy[r][lane+32];
            float sm = va + vb, sq = va*va + vb*vb;
            #pragma unroll
            for (int o=16;o;o>>=1){
                sm += __shfl_xor_sync(0xffffffffu, sm, o);
                sq += __shfl_xor_sync(0xffffffffu, sq, o);
            }
            if (lane == 0){
                float mean = sm * 0.015625f;
                float var  = sq * 0.015625f - mean*mean;
                sh_stat[r][0] = mean;
                sh_stat[r][1] = rsqrtf(var + 1e-5f);
            }
        }
    };
    auto ln_chain = [&](float (*hstate)[64], float* hn_out,
                        float lag_r, float lab_r, float log_r, float lob_r){
        ln_pass();
        __syncthreads();
        #pragma unroll
        for (int q=0;q<2;q++){
            int r = myr[q];
            float v  = sh_hy[r][m];
            float ln = (v - sh_stat[r][0]) * sh_stat[r][1] * lag_r + lab_r;
            float yv = ln + hstate[r][m];
            if (q < nmy) sh_hy[r][m] = yv;
        }
        __syncthreads();
        ln_pass();
        __syncthreads();
        #pragma unroll
        for (int q=0;q<2;q++){
            int r = myr[q];
            float yv = sh_hy[r][m];
            float hn = (yv - sh_stat[r][0]) * sh_stat[r][1] * log_r + lob_r;
            hn_out[q] = hn;
            if (q < nmy) hstate[r][m] = hn;
        }
    };

    // attn: a[r][m2..m2+1] = ba + hy[r]@Wa  (32 k-pairs, f32x2)
    auto attn_stage = [&](int l){
        if (wrp < nrows){
            int r = wrp;
            u64t a0 = pk2(sb_ba[l][m2], 0.f), a1 = pk2(sb_ba[l][m2+1], 0.f);
            #pragma unroll 8
            for (int p=0;p<32;p++){
                ulonglong2 w = panu[p*32 + cg];
                u64t z = *(const u64t*)&sh_hy[r][2*p];
                a0 = fma2(z, w.x, a0);
                a1 = fma2(z, w.y, a1);
            }
            *(float2*)&sh_a[r][m2] = make_float2(red2(a0), red2(a1));
        }
    };
    auto ff1_stage = [&](int l){
        u64t t00 = pk2(sb_b1[l][n2b], 0.f), t01 = pk2(sb_b1[l][n2b+1], 0.f);
        u64t t10 = t00, t11 = t01;
        #pragma unroll 8
        for (int p=0;p<32;p++){
            ulonglong2 w = panu[p*64 + cgf];
            u64t zA = *(const u64t*)&sh_a[rA][2*p];
            u64t zB = *(const u64t*)&sh_a[rB][2*p];
            t00 = fma2(zA, w.x, t00); t01 = fma2(zA, w.y, t01);
            t10 = fma2(zB, w.x, t10); t11 = fma2(zB, w.y, t11);
        }
        const float c = 0.7071067811865475f;
        float v00 = red2(t00), v01 = red2(t01), v10 = red2(t10), v11 = red2(t11);
        float g00 = 0.5f*v00*(1.0f + erff(v00*c));
        float g01 = 0.5f*v01*(1.0f + erff(v01*c));
        *(float2*)&sh_t1[rA][n2b] = make_float2(g00, g01);
        if (hasB){
            float g10 = 0.5f*v10*(1.0f + erff(v10*c));
            float g11 = 0.5f*v11*(1.0f + erff(v11*c));
            *(float2*)&sh_t1[rB][n2b] = make_float2(g10, g11);
        }
    };
    auto ff2_stage = [&](int l){
        if (wrp < nrows){
            int r = wrp;
            u64t a0 = pk2(sb_b2[l][m2], 0.f), a1 = pk2(sb_b2[l][m2+1], 0.f);
            #pragma unroll 8
            for (int p=0;p<64;p++){
                ulonglong2 w = panu[p*32 + cg];
                u64t z = *(const u64t*)&sh_t1[r][2*p];
                a0 = fma2(z, w.x, a0);
                a1 = fma2(z, w.y, a1);
            }
            *(float2*)&sh_hy[r][m2] = make_float2(red2(a0), red2(a1));
        }
    };

    for (int t=0; t<512; t++){
        cpyp<GW0_A>(pan4, gw0g, tid);
        {
            float srcf = fmaxf((t + 0.5f) * scf - 0.5f, 0.0f);
            int i0 = (int)srcf;
            if (i0 > Li-1) i0 = Li-1;
            int i1 = min(i0+1, Li-1);
            float wu = srcf - (float)i0;
            if (tid < nrows*12){
                int r = tid/12, k = tid%12;
                const float* xb = x + ((size_t)(base+r)*512 + st0)*12;
                float va = xb[i0*12 + k], vb = xb[i1*12 + k];
                sh_x[r][k] = va*(1.0f - wu) + vb*wu;
            }
        }
        __syncthreads();                              // S1: gw0A(pairs0..19) + sh_x ready

        // ---- gates layer 0 (f32x2, plane-split contiguous loads) ----
        u64t aF[2], aI[2], aG[2], aO[2];
        #pragma unroll
        for (int q=0;q<2;q++){
            aF[q] = pk2(r_gb0f, 0.f); aI[q] = pk2(r_gb0i, 0.f);
            aG[q] = pk2(r_gb0g, 0.f); aO[q] = pk2(r_gb0o, 0.f);
        }
        #pragma unroll
        for (int p=0;p<6;p++){                        // k 0..11 from sh_x
            ulonglong2 wfi = panu[p*128 + m], wgo = panu[p*128 + 64 + m];
            #pragma unroll
            for (int q=0;q<2;q++){
                u64t z = *(const u64t*)&sh_x[myr[q]][2*p];
                aF[q] = fma2(z, wfi.x, aF[q]); aI[q] = fma2(z, wfi.y, aI[q]);
                aG[q] = fma2(z, wgo.x, aG[q]); aO[q] = fma2(z, wgo.y, aO[q]);
            }
        }
        #pragma unroll 7
        for (int p=6;p<20;p++){                       // k 12..39 from sh_h0
            ulonglong2 wfi = panu[p*128 + m], wgo = panu[p*128 + 64 + m];
            #pragma unroll
            for (int q=0;q<2;q++){
                u64t z = *(const u64t*)&sh_h0[myr[q]][2*p-12];
                aF[q] = fma2(z, wfi.x, aF[q]); aI[q] = fma2(z, wfi.y, aI[q]);
                aG[q] = fma2(z, wgo.x, aG[q]); aO[q] = fma2(z, wgo.y, aO[q]);
            }
        }
        __syncthreads();                              // S2: panel free
        cpyp<GW0_B>(pan4, gw0g + GW0_A, tid);
        __syncthreads();                              // S3: gw0B(pairs20..37) ready
        #pragma unroll 6
        for (int p=20;p<38;p++){                      // k 40..75 from sh_h0
            ulonglong2 wfi = panu[(p-20)*128 + m], wgo = panu[(p-20)*128 + 64 + m];
            #pragma unroll
            for (int q=0;q<2;q++){
                u64t z = *(const u64t*)&sh_h0[myr[q]][2*p-12];
                aF[q] = fma2(z, wfi.x, aF[q]); aI[q] = fma2(z, wfi.y, aI[q]);
                aG[q] = fma2(z, wgo.x, aG[q]); aO[q] = fma2(z, wgo.y, aO[q]);
            }
        }
        #pragma unroll
        for (int q=0;q<2;q++){
            float cn = sigmf(red2(aF[q]))*c0r[q] + sigmf(red2(aI[q]))*tanhfast(red2(aG[q]));
            float ht = sigmf(red2(aO[q]))*tanhfast(cn);
            if (q < nmy){ c0r[q] = cn; sh_hy[myr[q]][m] = ht; }
        }
        __syncthreads();                              // S4
        cpyp<1024>(pan4, Wa0_4, tid);
        __syncthreads();                              // S5
        attn_stage(0);
        __syncthreads();                              // S6
        cpyp<2048>(pan4, w10_4, tid);
        __syncthreads();                              // S7
        ff1_stage(0);
        __syncthreads();                              // S8
        cpyp<2048>(pan4, w20_4, tid);
        __syncthreads();                              // S9
        ff2_stage(0);
        __syncthreads();                              // S10
        float h0n[2];
        ln_chain(sh_h0, h0n, r_lag0, r_lab0, r_log0, r_lob0);
        #pragma unroll
        for (int q=0;q<2;q++){
            int r = myr[q];
            float acc = h0n[q] + r_rb0;
            #pragma unroll
            for (int k=0;k<12;k++) acc += sh_x[r][k] * s_rw0[k*64 + m];
            if (q < nmy) sh_inp[r][m] = acc;
        }
        __syncthreads();                              // S14
        cpyp<1024>(pan4, Wa1_4, tid);

        // ---- gates layer 1 (resident, f32x2, plane-split) ----
        #pragma unroll
        for (int q=0;q<2;q++){
            aF[q] = pk2(r_gb1f, 0.f); aI[q] = pk2(r_gb1i, 0.f);
            aG[q] = pk2(r_gb1g, 0.f); aO[q] = pk2(r_gb1o, 0.f);
        }
        #pragma unroll 8
        for (int p=0;p<32;p++){                       // k 0..63 from sh_inp
            ulonglong2 wfi = gw1u[p*128 + m], wgo = gw1u[p*128 + 64 + m];
            #pragma unroll
            for (int q=0;q<2;q++){
                u64t z = *(const u64t*)&sh_inp[myr[q]][2*p];
                aF[q] = fma2(z, wfi.x, aF[q]); aI[q] = fma2(z, wfi.y, aI[q]);
                aG[q] = fma2(z, wgo.x, aG[q]); aO[q] = fma2(z, wgo.y, aO[q]);
            }
        }
        #pragma unroll 8
        for (int p=32;p<64;p++){                      // k 64..127 from sh_h1
            ulonglong2 wfi = gw1u[p*128 + m], wgo = gw1u[p*128 + 64 + m];
            #pragma unroll
            for (int q=0;q<2;q++){
                u64t z = *(const u64t*)&sh_h1[myr[q]][2*p-64];
                aF[q] = fma2(z, wfi.x, aF[q]); aI[q] = fma2(z, wfi.y, aI[q]);
                aG[q] = fma2(z, wgo.x, aG[q]); aO[q] = fma2(z, wgo.y, aO[q]);
            }
        }
        #pragma unroll
        for (int q=0;q<2;q++){
            float cn = sigmf(red2(aF[q]))*c1r[q] + sigmf(red2(aI[q]))*tanhfast(red2(aG[q]));
            float ht = sigmf(red2(aO[q]))*tanhfast(cn);
            if (q < nmy){ c1r[q] = cn; sh_hy[myr[q]][m] = ht; }
        }
        __syncthreads();                              // S15: Wa1 + hy ready
        attn_stage(1);
        __syncthreads();                              // S16
        cpyp<2048>(pan4, w11_4, tid);
        __syncthreads();                              // S17
        ff1_stage(1);
        __syncthreads();                              // S18
        cpyp<2048>(pan4, w21_4, tid);
        __syncthreads();                              // S19
        ff2_stage(1);
        __syncthreads();                              // S20
        float h1n[2];
        ln_chain(sh_h1, h1n, r_lag1, r_lab1, r_log1, r_lob1);
        __syncthreads();                              // S24

        // ---- out = h1 + inp@rw1 + rb1 (f32x2, resident transposed rw1) ----
        if (wrp < nrows){
            int r = wrp;
            u64t a0 = pk2(sb_rb1[m2]   + sh_h1[r][m2],   0.f);
            u64t a1 = pk2(sb_rb1[m2+1] + sh_h1[r][m2+1], 0.f);
            const ulonglong2* rwu = (const ulonglong2*)s_rw1;
            #pragma unroll 8
            for (int p=0;p<32;p++){
                ulonglong2 w = rwu[p*32 + cg];
                u64t z = *(const u64t*)&sh_inp[r][2*p];
                a0 = fma2(z, w.x, a0);
                a1 = fma2(z, w.y, a1);
            }
            ((float2*)(outbase + ((size_t)r*512 + t)*64))[cg] = make_float2(red2(a0), red2(a1));
        }
        __syncthreads();                              // S25
    }
}

__global__ void merge_kernel(const float* __restrict__ attn_w, float* __restrict__ out){
    int warp = (blockIdx.x*blockDim.x + threadIdx.x) >> 5;
    int lane = threadIdx.x & 31;
    if (warp >= 512*512) return;
    const size_t SS = 512ull*512*64;
    const float* p = g_outs + (size_t)warp*64;
    float aw0 = attn_w[lane], aw1 = attn_w[lane+32];
    float v0[3], v1[3], sc[3];
    #pragma unroll
    for (int si=0; si<3; si++){
        v0[si] = p[si*SS + lane];
        v1[si] = p[si*SS + lane + 32];
        float d = v0[si]*aw0 + v1[si]*aw1;
        #pragma unroll
        for (int o=16;o;o>>=1) d += __shfl_xor_sync(0xffffffffu, d, o);
        sc[si] = d;
    }
    float mx = fmaxf(sc[0], fmaxf(sc[1], sc[2]));
    float e0 = __expf(sc[0]-mx), e1 = __expf(sc[1]-mx), e2 = __expf(sc[2]-mx);
    float inv = __fdividef(1.0f, e0+e1+e2);
    float wt0 = e0*inv, wt1 = e1*inv, wt2 = e2*inv;
    out[(size_t)warp*64 + lane]      = v0[0]*wt0 + v0[1]*wt1 + v0[2]*wt2;
    out[(size_t)warp*64 + lane + 32] = v1[0]*wt0 + v1[1]*wt1 + v1[2]*wt2;
}

extern "C" void kernel_launch(void* const* d_in, const int* in_sizes, int n_in,
                              void* d_out, int out_size){
    const float* x     = (const float*)d_in[0];
    const float* gw0   = (const float*)d_in[1];
    const float* gb0   = (const float*)d_in[2];
    const float* gw1   = (const float*)d_in[3];
    const float* gb1   = (const float*)d_in[4];
    const float* mi_w  = (const float*)d_in[5];
    const float* mi_b  = (const float*)d_in[6];
    const float* mo_w  = (const float*)d_in[7];
    const float* mo_b  = (const float*)d_in[8];
    const float* w1    = (const float*)d_in[9];
    const float* b1    = (const float*)d_in[10];
    const float* w2    = (const float*)d_in[11];
    const float* b2    = (const float*)d_in[12];
    const float* lag   = (const float*)d_in[13];
    const float* lab   = (const float*)d_in[14];
    const float* logw  = (const float*)d_in[15];
    const float* lob   = (const float*)d_in[16];
    const float* rw0   = (const float*)d_in[17];
    const float* rb0   = (const float*)d_in[18];
    const float* rw1   = (const float*)d_in[19];
    const float* rb1   = (const float*)d_in[20];
    const float* attnw = (const float*)d_in[21];
    float* out = (float*)d_out;

    static int smem_set = 0;
    if (!smem_set){
        cudaFuncSetAttribute(xlstm_kernel, cudaFuncAttributeMaxDynamicSharedMemorySize, DYN_SMEM);
        smem_set = 1;
    }

    pack_gw_kernel<<<(3*128*256 + 255)/256, 256>>>(gw0, gw1);
    pack_t_kernel<<<(6*64*128 + 255)/256, 256>>>(w1, w2, rw1);
    compute_wa_kernel<<<6, 256>>>(mi_w, mi_b, mo_w, mo_b);
    xlstm_kernel<<<NCTA, T, DYN_SMEM>>>(x, gb0, gb1, b1, b2,
                                        lag, lab, logw, lob, rw0, rb0, rb1);
    merge_kernel<<<(512*512*32 + 255)/256, 256>>>(attnw, out);
}